// round 17
// baseline (speedup 1.0000x reference)
#include <cuda_runtime.h>
#include <cuda_fp16.h>
#include <math.h>
#include <stdint.h>

#define T_STEPS 256
#define BATCH   256
#define OBSD    128
#define HIDD    256
#define HS      512
#define G4      2048
#define ACTD    16
#define TBROWS  (T_STEPS * BATCH)
#define NCTA    128
typedef __half HF;

// ---------------- scratch (static device arrays; no cudaMalloc) ----------------
__device__ __align__(16) HF    g_fH[(size_t)TBROWS * HIDD];   // feats fp16
__device__ __align__(16) HF    g_hH[(size_t)TBROWS * HS];     // h fp16
__device__ __align__(16) HF    g_Wh[(size_t)G4 * HS];         // [n][k] permuted+transposed fp16
__device__ __align__(16) HF    g_Wi[(size_t)G4 * HIDD];
__device__ __align__(16) float g_bP[G4];
__device__ __align__(128) unsigned g_cntA[128];               // per-mb barrier counters (mb*32)

__device__ __forceinline__ float sigmf(float x) { return 1.0f / (1.0f + expf(-x)); }
__device__ __forceinline__ float geluf(float v) {
    float u = 0.7978845608028654f * (v + 0.044715f * v * v * v);
    return 0.5f * v * (1.0f + tanhf(u));
}
__device__ __forceinline__ uint32_t smem_u32(const void* p) {
    uint32_t a;
    asm("{ .reg .u64 t; cvta.to.shared.u64 t, %1; cvt.u32.u64 %0, t; }" : "=r"(a) : "l"(p));
    return a;
}
__device__ __forceinline__ void ldmx4(uint32_t addr, uint32_t* r) {
    asm volatile("ldmatrix.sync.aligned.m8n8.x4.shared.b16 {%0,%1,%2,%3}, [%4];"
        : "=r"(r[0]), "=r"(r[1]), "=r"(r[2]), "=r"(r[3]) : "r"(addr));
}
__device__ __forceinline__ void mma16816(float* d, const uint32_t* a, const uint32_t* b) {
    asm volatile("mma.sync.aligned.m16n8k16.row.col.f32.f16.f16.f32 "
        "{%0,%1,%2,%3}, {%4,%5,%6,%7}, {%8,%9}, {%0,%1,%2,%3};"
        : "+f"(d[0]), "+f"(d[1]), "+f"(d[2]), "+f"(d[3])
        : "r"(a[0]), "r"(a[1]), "r"(a[2]), "r"(a[3]), "r"(b[0]), "r"(b[1]));
}
#define CP_COMMIT() asm volatile("cp.async.commit_group;" ::: "memory")
#define CP_WAIT0()  asm volatile("cp.async.wait_group 0;" ::: "memory")
#define CP_WAIT1()  asm volatile("cp.async.wait_group 1;" ::: "memory")
__device__ __forceinline__ void flag_arrive(unsigned* f) {
    asm volatile("red.release.gpu.global.add.u32 [%0], %1;" :: "l"(f), "r"(1u) : "memory");
}
__device__ __forceinline__ void flag_spin(const unsigned* f, unsigned target) {
    unsigned v;
    do {
        asm volatile("ld.acquire.gpu.global.u32 %0, [%1];" : "=r"(v) : "l"(f) : "memory");
    } while (v < target);
}

// A stage stride: 136 halves (272B, ≡16 mod 128 -> conflict-free ldmatrix)
#define AST 136
#define CHUNK_BYTES 17408          // 64 x 136 halves
// ---- scan SMEM map (bytes) ----
#define S_WH   0                   // Wh slice 64x520 halves = 66560
#define S_WI   66560               // Wi slice 64x264 halves = 33792
#define S_HB   100352              // h stage: 4 chunks x 17408 = 69632
#define S_FB   169984              // feats stage: 2 sub-chunks of 17408 = 34816
#define S_BS   204800              // bias slice 64 f32 = 256
#define S_DYN  205056
#define WST_H  520
#define WST_I  264

// cp.async one K=128 chunk (64 rows) of fp16 A into stage buffer (512 thr)
__device__ __forceinline__ void stage_cp(uint32_t dst, const HF* src, int ld, int tid) {
#pragma unroll
    for (int p = 0; p < 2; p++) {
        int j = tid + p * 512;
        int r = j >> 4, cb = j & 15;
        const HF* s = src + (size_t)r * ld + cb * 8;
        uint32_t d = dst + r * 272 + cb * 16;
        asm volatile("cp.async.cg.shared.global [%0], [%1], 16;" :: "r"(d), "l"(s));
    }
}

// Warp (mg, ng): m16 x n16 tile, FULL-K: 8 ksteps of one 128-col A chunk
// against W ksteps wkbase+0..7. acc[2][4] = complete output fragment.
__device__ __forceinline__ void mma_chunk_full(uint32_t aBuf, uint32_t wBuf, int wst,
                                               int wkbase, int mg, int ng, int lane,
                                               float acc[2][4]) {
    int nrow = ng * 16 + (lane & 7) + ((lane >> 4) << 3);
    int arow = mg * 16 + (lane & 15);
#pragma unroll
    for (int s = 0; s < 8; s++) {
        uint32_t bh[4], ah[4];
        int kcol = (wkbase + s) * 16 + ((lane >> 3) & 1) * 8;
        ldmx4(wBuf + (nrow * wst + kcol) * 2, bh);
        int col = s * 16 + ((lane >> 4) << 3);
        ldmx4(aBuf + (arow * AST + col) * 2, ah);
        mma16816(acc[0], ah, &bh[0]);
        mma16816(acc[1], ah, &bh[2]);
    }
}

// ---------------- prep: permuted+transposed fp16 weights ----------------
__global__ void prep_kernel(const float* __restrict__ Wi, const float* __restrict__ Wh,
                            const float* __restrict__ bl) {
    int stride = gridDim.x * blockDim.x;
    int idx = blockIdx.x * blockDim.x + threadIdx.x;
    for (int i = idx; i < G4 * HS; i += stride) {
        int n = i >> 9, k = i & (HS - 1);
        g_Wh[i] = __float2half(Wh[(size_t)k * G4 + (n & 3) * HS + (n >> 2)]);
    }
    for (int i = idx; i < G4 * HIDD; i += stride) {
        int n = i >> 8, k = i & (HIDD - 1);
        g_Wi[i] = __float2half(Wi[(size_t)k * G4 + (n & 3) * HS + (n >> 2)]);
    }
    for (int i = idx; i < G4; i += stride)
        g_bP[i] = bl[(i & 3) * HS + (i >> 2)];
    if (idx < 128) g_cntA[idx] = 0;
}

// ---------------- encoder: feats = gelu(x@W_enc + b) -> fp16 ----------------
__global__ void __launch_bounds__(256) enc_kernel(const float* __restrict__ A,
                                                  const float* __restrict__ B,
                                                  const float* __restrict__ bias) {
    __shared__ float As[64 * 68];
    __shared__ float Bs[64 * 64];
    int nb = blockIdx.x, mb = blockIdx.y, tid = threadIdx.x;
    int tn = tid & 15, tm = tid >> 4;
    float acc[4][4];
#pragma unroll
    for (int i = 0; i < 4; i++)
#pragma unroll
        for (int j = 0; j < 4; j++) acc[i][j] = 0.f;
    for (int kc = 0; kc < 2; kc++) {
        __syncthreads();
#pragma unroll
        for (int p = 0; p < 4; p++) {
            int idx = p * 256 + tid, r = idx >> 4, c4 = (idx & 15) << 2;
            *(float4*)&As[r * 68 + c4] = *(const float4*)&A[(size_t)(mb * 64 + r) * OBSD + kc * 64 + c4];
            *(float4*)&Bs[r * 64 + c4] = *(const float4*)&B[(size_t)(kc * 64 + r) * HIDD + nb * 64 + c4];
        }
        __syncthreads();
#pragma unroll 8
        for (int kk = 0; kk < 64; kk++) {
            float4 w = *(const float4*)&Bs[kk * 64 + tn * 4];
#pragma unroll
            for (int i = 0; i < 4; i++) {
                float a = As[(tm * 4 + i) * 68 + kk];
                acc[i][0] += a * w.x; acc[i][1] += a * w.y;
                acc[i][2] += a * w.z; acc[i][3] += a * w.w;
            }
        }
    }
    int n0 = nb * 64 + tn * 4;
    float4 bb = *(const float4*)&bias[n0];
#pragma unroll
    for (int i = 0; i < 4; i++) {
        int row = mb * 64 + tm * 4 + i;
        __align__(8) HF hb[4];
        hb[0] = __float2half(geluf(acc[i][0] + bb.x));
        hb[1] = __float2half(geluf(acc[i][1] + bb.y));
        hb[2] = __float2half(geluf(acc[i][2] + bb.z));
        hb[3] = __float2half(geluf(acc[i][3] + bb.w));
        *(int2*)(g_fH + (size_t)row * HIDD + n0) = *(int2*)hb;
    }
}

// ---------------- fused persistent LSTM scan (full-K warps, register epilogue) ----------------
// 128 CTAs = 4 mb(64 batch) x 32 nb(64 gate cols). 16 warps = 4 mg x 4 ng,
// each warp owns an m16 x n16 output tile over the FULL K (feats 256 + h 512).
// Epilogue: gates gathered via one shfl_xor(1) pair exchange; c lives in registers.
__global__ void __launch_bounds__(512) scan_mma_kernel() {
    extern __shared__ char sm[];
    uint32_t sb = smem_u32(sm);
    float* bS = (float*)(sm + S_BS);
    int tid = threadIdx.x, lane = tid & 31, wid = tid >> 5;
    int mb = blockIdx.x >> 5, nb = blockIdx.x & 31;
    int mg = wid & 3, ng = wid >> 2;
    unsigned* ctr = &g_cntA[mb * 32];

    {   // resident Wh slice [64][512] + Wi slice [64][256] + bias
        HF* Wh = (HF*)(sm + S_WH);
        HF* Wi = (HF*)(sm + S_WI);
        const HF* sh = g_Wh + (size_t)(nb * 64) * HS;
        const HF* si = g_Wi + (size_t)(nb * 64) * HIDD;
        for (int i = tid; i < 4096; i += 512) {
            int r = i >> 6, c8 = (i & 63) * 8;
            *(int4*)&Wh[r * WST_H + c8] = *(const int4*)&sh[(size_t)r * HS + c8];
        }
        for (int i = tid; i < 2048; i += 512) {
            int r = i >> 5, c8 = (i & 31) * 8;
            *(int4*)&Wi[r * WST_I + c8] = *(const int4*)&si[(size_t)r * HIDD + c8];
        }
        if (tid < 64) bS[tid] = g_bP[nb * 64 + tid];
    }
    __syncthreads();

    const uint32_t hb = sb + S_HB;
    const uint32_t fb = sb + S_FB;
    int q = lane & 3, p = lane >> 2;
    bool even = (lane & 1) == 0;
    int erow = mb * 64 + mg * 16 + p + ((lane & 1) << 3);   // this thread's batch row
    float creg[2] = { 0.f, 0.f };                            // cell state in registers

    // prologue: stage feats tile for t=0
    {
        const HF* F = g_fH + (size_t)(mb * 64) * HIDD;
        stage_cp(fb, F, HIDD, tid);
        stage_cp(fb + CHUNK_BYTES, F + 128, HIDD, tid);
        CP_COMMIT();
    }

#pragma unroll 1
    for (int t = 0; t < T_STEPS; t++) {
        float acc[2][4];
#pragma unroll
        for (int b = 0; b < 2; b++)
#pragma unroll
            for (int e = 0; e < 4; e++) acc[b][e] = 0.f;

        if (t > 0) {
            // burst-stage all 4 h chunks (one group); feats(t) group pends ahead
            const HF* Ah = g_hH + ((size_t)(t - 1) * BATCH + mb * 64) * HS;
#pragma unroll
            for (int ch = 0; ch < 4; ch++)
                stage_cp(hb + ch * CHUNK_BYTES, Ah + ch * 128, HS, tid);
            CP_COMMIT();
            CP_WAIT1();                     // feats(t) resident (h may pend)
        } else {
            CP_WAIT0();
        }
        __syncthreads();

        // feats @ Wi — overlaps h burst arrival
        mma_chunk_full(fb, sb + S_WI, WST_I, 0, mg, ng, lane, acc);
        mma_chunk_full(fb + CHUNK_BYTES, sb + S_WI, WST_I, 8, mg, ng, lane, acc);

        if (t > 0) {
            CP_WAIT0();                     // all h chunks resident
            __syncthreads();
#pragma unroll
            for (int ch = 0; ch < 4; ch++)
                mma_chunk_full(hb + ch * CHUNK_BYTES, sb + S_WH, WST_H,
                               ch * 8, mg, ng, lane, acc);
        }

        // register epilogue: pair exchange gathers (i,f,g,o) per unit
#pragma unroll
        for (int nt = 0; nt < 2; nt++) {
            float sA = even ? acc[nt][2] : acc[nt][0];
            float sB = even ? acc[nt][3] : acc[nt][1];
            float rA = __shfl_xor_sync(0xffffffffu, sA, 1);
            float rB = __shfl_xor_sync(0xffffffffu, sB, 1);
            float zi, zf, zg, zo;
            if (even) { zi = acc[nt][0]; zf = acc[nt][1]; zg = rA; zo = rB; }
            else      { zi = rA; zf = rB; zg = acc[nt][2]; zo = acc[nt][3]; }
            int ul = ng * 4 + nt * 2 + (q >> 1);            // CTA-local unit
            float4 bb = *(const float4*)&bS[ul * 4];
            zi += bb.x; zf += bb.y; zg += bb.z; zo += bb.w;
            float cn = sigmf(zf) * creg[nt] + sigmf(zi) * tanhf(zg);
            creg[nt] = cn;
            float hv = sigmf(zo) * tanhf(cn);
            g_hH[(size_t)((size_t)t * BATCH + erow) * HS + nb * 16 + ul] = __float2half(hv);
        }

        // release h(t); stage feats(t+1) during the spin
        __syncthreads();                    // h stores done CTA-wide; fb reads done
        if (tid == 0) flag_arrive(ctr);
        if (t + 1 < T_STEPS) {
            const HF* F = g_fH + ((size_t)(t + 1) * BATCH + mb * 64) * HIDD;
            stage_cp(fb, F, HIDD, tid);
            stage_cp(fb + CHUNK_BYTES, F + 128, HIDD, tid);
            CP_COMMIT();                    // group: feats(t+1)
        }
        if (tid == 0) flag_spin(ctr, (unsigned)(t + 1) * 32u);
        __syncthreads();
    }
}

// ---------------- heads: 2 rows per warp share every Wt LDS (measured best) ----------------
__global__ void __launch_bounds__(256) heads_kernel(
    const float* __restrict__ Wmu, const float* __restrict__ bmu,
    const float* __restrict__ lstd, const float* __restrict__ Wv,
    const float* __restrict__ bv, float* __restrict__ out) {
    __shared__ float Wt[17 * HS];
    __shared__ float sig_s[16], bias_s[17];
    int tid = threadIdx.x;
    for (int i = tid; i < HS * ACTD; i += 256) {
        int k = i >> 4, a = i & 15;
        Wt[a * HS + k] = Wmu[(size_t)k * ACTD + a];
    }
    for (int i = tid; i < HS; i += 256) Wt[16 * HS + i] = Wv[i];
    if (tid < 16) { sig_s[tid] = expf(lstd[tid]); bias_s[tid] = bmu[tid]; }
    if (tid == 16) bias_s[16] = bv[0];
    __syncthreads();

    int warp = tid >> 5, lane = tid & 31;
    int step = gridDim.x * 16;
    for (int row = blockIdx.x * 16 + warp * 2; row < TBROWS; row += step) {
        const HF* h0 = g_hH + (size_t)row * HS;
        const HF* h1 = h0 + HS;
        float a0[17], a1[17];
#pragma unroll
        for (int a = 0; a < 17; a++) { a0[a] = 0.f; a1[a] = 0.f; }
#pragma unroll 4
        for (int q = 0; q < 16; q++) {
            int idx = q * 32 + lane;
            float v0 = __half2float(h0[idx]);
            float v1 = __half2float(h1[idx]);
#pragma unroll
            for (int a = 0; a < 17; a++) {
                float w = Wt[a * HS + idx];
                a0[a] += v0 * w; a1[a] += v1 * w;
            }
        }
#pragma unroll
        for (int a = 0; a < 17; a++)
#pragma unroll
            for (int off = 16; off > 0; off >>= 1) {
                a0[a] += __shfl_xor_sync(0xffffffffu, a0[a], off);
                a1[a] += __shfl_xor_sync(0xffffffffu, a1[a], off);
            }
        if (lane < 16) {
            out[(size_t)row * ACTD + lane] = a0[lane] + bias_s[lane];
            out[(size_t)(row + 1) * ACTD + lane] = a1[lane] + bias_s[lane];
            out[(size_t)TBROWS * ACTD + (size_t)row * ACTD + lane] = sig_s[lane];
            out[(size_t)TBROWS * ACTD + (size_t)(row + 1) * ACTD + lane] = sig_s[lane];
        }
        if (lane == 0) {
            out[(size_t)TBROWS * ACTD * 2 + row] = a0[16] + bias_s[16];
            out[(size_t)TBROWS * ACTD * 2 + row + 1] = a1[16] + bias_s[16];
        }
    }
}

// ---------------- launch ----------------
extern "C" void kernel_launch(void* const* d_in, const int* in_sizes, int n_in,
                              void* d_out, int out_size) {
    const float* x     = (const float*)d_in[0];
    const float* W_enc = (const float*)d_in[1];
    const float* b_enc = (const float*)d_in[2];
    const float* Wi    = (const float*)d_in[3];
    const float* Wh    = (const float*)d_in[4];
    const float* b_l   = (const float*)d_in[5];
    const float* W_mu  = (const float*)d_in[6];
    const float* b_mu  = (const float*)d_in[7];
    const float* lstd  = (const float*)d_in[8];
    const float* W_v   = (const float*)d_in[9];
    const float* b_v   = (const float*)d_in[10];
    float* out = (float*)d_out;

    cudaFuncSetAttribute(scan_mma_kernel, cudaFuncAttributeMaxDynamicSharedMemorySize, S_DYN);

    prep_kernel<<<1024, 256>>>(Wi, Wh, b_l);
    enc_kernel<<<dim3(HIDD / 64, TBROWS / 64), 256>>>(x, W_enc, b_enc);
    scan_mma_kernel<<<NCTA, 512, S_DYN>>>();
    heads_kernel<<<1024, 256>>>(W_mu, b_mu, lstd, W_v, b_v, out);
}